// round 12
// baseline (speedup 1.0000x reference)
#include <cuda_runtime.h>
#include <math.h>

#define NQb 12
#define SDIM 4096
#define TPB 256

typedef unsigned long long u64;

// ---------- packed f32x2 helpers ----------
__device__ __forceinline__ u64 pk2(float lo, float hi) {
    u64 r; asm("mov.b64 %0,{%1,%2};" : "=l"(r) : "f"(lo), "f"(hi)); return r;
}
__device__ __forceinline__ void unpk2(u64 v, float& lo, float& hi) {
    asm("mov.b64 {%0,%1},%2;" : "=f"(lo), "=f"(hi) : "l"(v));
}
__device__ __forceinline__ u64 f2mul(u64 a, u64 b) {
    u64 d; asm("mul.rn.f32x2 %0,%1,%2;" : "=l"(d) : "l"(a), "l"(b)); return d;
}
__device__ __forceinline__ u64 f2fma(u64 a, u64 b, u64 c) {
    u64 d; asm("fma.rn.f32x2 %0,%1,%2,%3;" : "=l"(d) : "l"(a), "l"(b), "l"(c)); return d;
}
__device__ __forceinline__ u64 cswap(u64 v) {
    float x, y; unpk2(v, x, y); return pk2(y, x);
}
__device__ __forceinline__ u64 cmulp(u64 a, float br, float bi) {   // a*(br+i bi)
    return f2fma(pk2(-bi, bi), cswap(a), f2mul(pk2(br, br), a));
}
__device__ __forceinline__ u64 cmul2(u64 a, u64 b) {
    float br, bi; unpk2(b, br, bi); return cmulp(a, br, bi);
}

// swizzle beta: conflict-free per 16-lane phase for pass A/B/C and tau-store
__device__ __forceinline__ int beta_s(int k) { return k ^ ((k >> 4) & 15); }

// CNOT-chain permutation (verified): state_after[k] = state_before[sigma(k)]
__device__ __forceinline__ int sigma12(int x) {
    x ^= (x & 1) << 11;
#pragma unroll
    for (int p = 1; p <= 11; ++p) x ^= ((x >> p) & 1) << (p - 1);
    return x;
}
// tau = sigma^{-1}
__device__ __forceinline__ int tau12(int x) {
#pragma unroll
    for (int p = 11; p >= 1; --p) x ^= ((x >> p) & 1) << (p - 1);
    x ^= (x & 1) << 11;
    return x;
}

// 4 RY rotations via lifting: reg bit bb <-> qubit (QHI-bb).
// Pass-A variant: bit0's coefficients passed explicitly (t0-signed).
template <int QHI>
__device__ __forceinline__ void ry4_liftA(u64 a[16], float p0, float q0,
                                          const float* __restrict__ tpL,
                                          const float* __restrict__ sryL) {
#pragma unroll
    for (int bb = 0; bb < 4; ++bb) {
        const float p = bb ? tpL[QHI - bb] : p0;
        const float q = bb ? sryL[QHI - bb] : q0;
        const u64 pp = pk2(p, p), qq = pk2(q, q);
        const int m = 1 << bb;
#pragma unroll
        for (int j0 = 0; j0 < 16; ++j0) {
            if (j0 & m) continue;
            const int j1 = j0 | m;
            a[j0] = f2fma(pp, a[j1], a[j0]);
            a[j1] = f2fma(qq, a[j0], a[j1]);
            a[j0] = f2fma(pp, a[j1], a[j0]);
        }
    }
}
template <int QHI>
__device__ __forceinline__ void ry4_lift(u64 a[16], const float* __restrict__ tpL,
                                         const float* __restrict__ sryL) {
    ry4_liftA<QHI>(a, tpL[QHI], sryL[QHI], tpL, sryL);
}

__global__ void __launch_bounds__(TPB, 4)
qsim_kernel(const float* __restrict__ xin, const float* __restrict__ params,
            const float* __restrict__ lin_w, const float* __restrict__ lin_b,
            float* __restrict__ out) {
    __shared__ __align__(16) u64 samp[SDIM];   // packed (re,im), slot beta(k)
    __shared__ u64 TLs[64], THs[64];           // layer-0 product tables
    __shared__ float2 sv[NQb][2];
    __shared__ float sry[60];                  // sin(th) (lifting q), layers 1..5
    __shared__ float tP[60];                   // -tan(th/2) (lifting p)
    __shared__ float tz[48];                   // RZ angles, layers 1..4
    __shared__ float2 Fj[4][16];               // RZ phase factors e^{i zoff(j)} per layer
    __shared__ float Tsum[4];
    __shared__ float red8[8];

    const int t = threadIdx.x;                 // 8 bits
    const int blk = blockIdx.x;
    const int lane = t & 31;
    const int t0 = t & 1;

    // ---------- setup ----------
    if (t < NQb) {
        const float h = tanhf(xin[blk * NQb + t]) * 1.5707963267948966f;
        const float ce = cosf(h), se = sinf(h);
        const float th = 0.5f * params[t];
        const float ct = cosf(th), st = sinf(th);
        const float a = ct * ce - st * se, b = st * ce + ct * se;
        const float tt0 = params[NQb + t];
        const float c0 = cosf(0.5f * tt0), s0 = sinf(0.5f * tt0);
        sv[t][0] = make_float2(a * c0, -a * s0);
        sv[t][1] = make_float2(b * c0,  b * s0);
    }
    if (t < 60) {
        const int L = t / NQb, q = t - L * NQb;
        const float th = 0.5f * params[(L + 1) * 24 + q];
        sry[t] = sinf(th);
        tP[t] = -tanf(0.5f * th);
    }
    if (t < 48) {
        const int L = t / NQb, q = t - L * NQb;
        tz[t] = params[(L + 1) * 24 + NQb + q];
    }
    __syncthreads();

    // product tables: TL over qubits 11..6 (k bits 0-5), TH over qubits 5..0 (k bits 6-11)
    if (t < 128) {
        const int n = t & 63;
        const int qb = (t < 64) ? 11 : 5;
        float2 a = sv[qb][n & 1];
#pragma unroll
        for (int p = 1; p < 6; ++p) {
            const float2 w = sv[qb - p][(n >> p) & 1];
            a = make_float2(a.x * w.x - a.y * w.y, a.x * w.y + a.y * w.x);
        }
        if (t < 64) TLs[n] = pk2(a.x, a.y); else THs[n] = pk2(a.x, a.y);
    }
    if (t < 64) {   // Fj[L][j]: e^{i*zoff}, pass-C reg bit bb (k bit 8+bb) <-> qubit (3-bb)
        const int L = t >> 4, j = t & 15;
        const float* tzL = tz + L * NQb;
        float zo = 0.f;
#pragma unroll
        for (int bb = 0; bb < 4; ++bb)
            if ((j >> bb) & 1) zo += tzL[3 - bb];
        float sz, cz; __sincosf(zo, &sz, &cz);
        Fj[L][j] = make_float2(cz, sz);
    }
    if (t >= 128 && t < 132) {
        const int L = t - 128; float s = 0.f;
#pragma unroll
        for (int q = 0; q < NQb; ++q) s += tz[L * NQb + q];
        Tsum[L] = s;
    }
    __syncthreads();

    // ---------- per-thread invariants ----------
    // pass A (slot-indexed pairs): thread slots = AbaseV ^ i, 16B-pair aligned
    const int AbaseV = ((t << 4) ^ (t & 15)) & ~1;     // beta(t<<4) with bit0 cleared
    const float sgn0 = t0 ? -1.f : 1.f;                // bit0 orientation sign
    const int Bbase = (t & 15) | ((t >> 4) << 8);      // beta(kB) = Bbase ^ (j<<4) ^ j
    const int Cbase = t ^ ((t >> 4) & 15);             // beta(kC) = Cbase ^ (j<<8)
    const int PT_t  = beta_s(tau12(t));                // tau-store, t-part
    const int TAU_t = tau12(t);                        // measurement fold

    // ---------- layer-1 pass-A input: layer 0 + CNOT folded (slot-pair layout) ----------
    // register i holds k-low = i ^ t0  ->  fold t0 into the sigma offset
    const int S_tA = sigma12(t << 4) ^ (t0 ? 0xC01 : 0);   // sigma12(1) = 0xC01
    u64 amp[16];
#pragma unroll
    for (int i = 0; i < 16; ++i) {
        const int m = S_tA ^ sigma12(i);
        amp[i] = cmul2(TLs[m & 63], THs[(m >> 6) & 63]);
    }

    float accm = 0.f;

#pragma unroll 1
    for (int L = 0; L < 5; ++L) {          // physical layers 1..5
        const float* tpL  = tP  + L * NQb;
        const float* sryL = sry + L * NQb;

        // pass A: k bits 0-3 on regs <-> qubits 11..8 (slot-indexed, 128-bit, in-place)
        if (L) {
#pragma unroll
            for (int i = 0; i < 16; i += 2) {
                const ulonglong2 v = *reinterpret_cast<const ulonglong2*>(&samp[AbaseV ^ i]);
                amp[i] = v.x; amp[i + 1] = v.y;
            }
        }
        ry4_liftA<11>(amp, sgn0 * tpL[11], sgn0 * sryL[11], tpL, sryL);
#pragma unroll
        for (int i = 0; i < 16; i += 2) {
            ulonglong2 v; v.x = amp[i]; v.y = amp[i + 1];
            *reinterpret_cast<ulonglong2*>(&samp[AbaseV ^ i]) = v;
        }
        __syncthreads();

        // pass B: k bits 4-7 on regs <-> qubits 7..4 (in-place per-thread)
#pragma unroll
        for (int j = 0; j < 16; ++j) amp[j] = samp[Bbase ^ ((j << 4) ^ j)];
        ry4_lift<7>(amp, tpL, sryL);
#pragma unroll
        for (int j = 0; j < 16; ++j) samp[Bbase ^ ((j << 4) ^ j)] = amp[j];
        __syncthreads();

        // pass C: k bits 8-11 on regs <-> qubits 3..0
#pragma unroll
        for (int j = 0; j < 16; ++j) amp[j] = samp[Cbase ^ (j << 8)];
        ry4_lift<3>(amp, tpL, sryL);

        if (L < 4) {
            // fused RZ via table: e^{i phase} = E_t * Fj[L][j]; one sincos per layer
            const float* tzL = tz + L * NQb;
            float phb = -0.5f * Tsum[L];
            if (t & 1)   phb += tzL[11];
            if (t & 2)   phb += tzL[10];
            if (t & 4)   phb += tzL[9];
            if (t & 8)   phb += tzL[8];
            if (t & 16)  phb += tzL[7];
            if (t & 32)  phb += tzL[6];
            if (t & 64)  phb += tzL[5];
            if (t & 128) phb += tzL[4];
            float es, ec; __sincosf(phb, &es, &ec);
            const float2* FjL = Fj[L];
#pragma unroll
            for (int j = 0; j < 16; ++j) {
                const float2 f = FjL[j];
                amp[j] = cmulp(cmulp(amp[j], f.x, f.y), ec, es);
            }
            __syncthreads();   // all pass-C loads consumed before permuted overwrite
            // CNOT fold: amp(kC) -> slot beta(tau(kC))
#pragma unroll
            for (int j = 0; j < 16; ++j)
                samp[PT_t ^ beta_s(tau12(j << 8))] = amp[j];
            __syncthreads();
        } else {
            // last layer: RZ is |.|^2-invariant; fold final CNOT into weights
            u64 accp = 0ull;
#pragma unroll
            for (int j = 0; j < 16; ++j) {
                const int tm = TAU_t ^ tau12(j << 8);
                const float w = (float)(NQb - 2 * __popc(tm));
                accp = f2fma(f2mul(amp[j], amp[j]), pk2(w, w), accp);
            }
            float wl, wh; unpk2(accp, wl, wh);
            accm = wl + wh;
        }
    }

    // ---------- reduction (8 warps) + head ----------
#pragma unroll
    for (int o = 16; o; o >>= 1) accm += __shfl_xor_sync(0xffffffffu, accm, o);
    if (lane == 0) red8[t >> 5] = accm;
    __syncthreads();
    if (t == 0) {
        float m = 0.f;
#pragma unroll
        for (int w = 0; w < 8; ++w) m += red8[w];
        const float z = (m / (float)NQb) * lin_w[0] + lin_b[0];
        out[blk] = 1.f / (1.f + expf(-z));
    }
}

extern "C" void kernel_launch(void* const* d_in, const int* in_sizes, int n_in,
                              void* d_out, int out_size) {
    const float* x      = (const float*)d_in[0];
    const float* params = (const float*)d_in[1];
    const float* lw     = (const float*)d_in[2];
    const float* lb     = (const float*)d_in[3];
    const int Bn = in_sizes[0] / NQb;      // 512
    qsim_kernel<<<Bn, TPB>>>(x, params, lw, lb, (float*)d_out);
}